// round 6
// baseline (speedup 1.0000x reference)
#include <cuda_runtime.h>
#include <cstdint>

// Problem constants (fixed by the dataset)
#define T_ 8
#define E_ 8388608
#define N_ 262144
#define F_ 64

// 8 MB scratch for segment sums, layout agg[n][t] row-major (32B per node).
// Zero-initialized at module load; gemm_kernel re-zeros it after consuming,
// so every kernel_launch invocation (and every graph replay) sees zeros.
__device__ float g_agg[(size_t)N_ * T_];

// ---------------------------------------------------------------------------
// Scatter-add: ONE edge per thread (measured fastest: max warp parallelism
// keeps the L1tex wavefront queue fed). 1x int2 index load, 8 coalesced
// feature loads, 2x red.global.add.v4.f32 into L2-resident agg.
// ---------------------------------------------------------------------------
__global__ void scatter_kernel(const float* __restrict__ feat,
                               const int2* __restrict__ idx) {
    int e = blockIdx.x * blockDim.x + threadIdx.x;

    int2 rc = __ldcs(&idx[e]);
    int row = rc.x & (N_ - 1);   // pow2 mask: no-op for valid rows, crash-proof otherwise
    float* dst = g_agg + (size_t)row * T_;

    float f0 = __ldcs(feat + 0 * (size_t)E_ + e);
    float f1 = __ldcs(feat + 1 * (size_t)E_ + e);
    float f2 = __ldcs(feat + 2 * (size_t)E_ + e);
    float f3 = __ldcs(feat + 3 * (size_t)E_ + e);
    asm volatile("red.global.add.v4.f32 [%0], {%1,%2,%3,%4};"
                 :: "l"(dst), "f"(f0), "f"(f1), "f"(f2), "f"(f3) : "memory");

    float f4 = __ldcs(feat + 4 * (size_t)E_ + e);
    float f5 = __ldcs(feat + 5 * (size_t)E_ + e);
    float f6 = __ldcs(feat + 6 * (size_t)E_ + e);
    float f7 = __ldcs(feat + 7 * (size_t)E_ + e);
    asm volatile("red.global.add.v4.f32 [%0], {%1,%2,%3,%4};"
                 :: "l"(dst + 4), "f"(f4), "f"(f5), "f"(f6), "f"(f7) : "memory");
}

// ---------------------------------------------------------------------------
// GEMM: out[n,f] = sum_t agg[n,t]*K[t,f] + bias[f].
// ONE-SHOT: each warp handles exactly 2 nodes (no grid-stride loop, so no
// loop-carried latency exposure; 131K warps hide everything).
// Lane layout: q = lane&15 owns f-quad [4q..4q+3]; lane>>4 picks the node.
// Per warp: 18 L1-resident LDG.128 (K+bias), 4 uniform LDG.128 (agg rows),
// 32 FMA warp-instrs, 2 coalesced STG.128 (.cs), 64B zeroing stores.
// ---------------------------------------------------------------------------
__global__ void gemm_kernel(const float* __restrict__ kern,
                            const float* __restrict__ bias,
                            float* __restrict__ out) {
    int lane = threadIdx.x & 31;
    int q    = lane & 15;     // f-quad 0..15
    int nsub = lane >> 4;     // 0..1

    float4 k4[T_];
    #pragma unroll
    for (int t = 0; t < T_; ++t)
        k4[t] = __ldg(reinterpret_cast<const float4*>(kern) + t * 16 + q);
    float4 acc = __ldg(reinterpret_cast<const float4*>(bias) + q);

    int warp_global = (blockIdx.x * blockDim.x + threadIdx.x) >> 5;
    int n = warp_global * 2 + nsub;          // < N_

    float4* arow = reinterpret_cast<float4*>(g_agg + (size_t)n * T_);
    float4 a0 = __ldcg(arow);                // uniform across 16 lanes
    float4 a1 = __ldcg(arow + 1);

    acc.x = fmaf(a0.x, k4[0].x, acc.x); acc.y = fmaf(a0.x, k4[0].y, acc.y);
    acc.z = fmaf(a0.x, k4[0].z, acc.z); acc.w = fmaf(a0.x, k4[0].w, acc.w);
    acc.x = fmaf(a0.y, k4[1].x, acc.x); acc.y = fmaf(a0.y, k4[1].y, acc.y);
    acc.z = fmaf(a0.y, k4[1].z, acc.z); acc.w = fmaf(a0.y, k4[1].w, acc.w);
    acc.x = fmaf(a0.z, k4[2].x, acc.x); acc.y = fmaf(a0.z, k4[2].y, acc.y);
    acc.z = fmaf(a0.z, k4[2].z, acc.z); acc.w = fmaf(a0.z, k4[2].w, acc.w);
    acc.x = fmaf(a0.w, k4[3].x, acc.x); acc.y = fmaf(a0.w, k4[3].y, acc.y);
    acc.z = fmaf(a0.w, k4[3].z, acc.z); acc.w = fmaf(a0.w, k4[3].w, acc.w);
    acc.x = fmaf(a1.x, k4[4].x, acc.x); acc.y = fmaf(a1.x, k4[4].y, acc.y);
    acc.z = fmaf(a1.x, k4[4].z, acc.z); acc.w = fmaf(a1.x, k4[4].w, acc.w);
    acc.x = fmaf(a1.y, k4[5].x, acc.x); acc.y = fmaf(a1.y, k4[5].y, acc.y);
    acc.z = fmaf(a1.y, k4[5].z, acc.z); acc.w = fmaf(a1.y, k4[5].w, acc.w);
    acc.x = fmaf(a1.z, k4[6].x, acc.x); acc.y = fmaf(a1.z, k4[6].y, acc.y);
    acc.z = fmaf(a1.z, k4[6].z, acc.z); acc.w = fmaf(a1.z, k4[6].w, acc.w);
    acc.x = fmaf(a1.w, k4[7].x, acc.x); acc.y = fmaf(a1.w, k4[7].y, acc.y);
    acc.z = fmaf(a1.w, k4[7].z, acc.z); acc.w = fmaf(a1.w, k4[7].w, acc.w);

    __stcs(reinterpret_cast<float4*>(out) + (size_t)n * 16 + q, acc);

    // consume-and-zero: 4 lanes per warp rewrite the two 32B agg rows.
    __syncwarp();
    if (q < 2)
        arow[q] = make_float4(0.f, 0.f, 0.f, 0.f);
}

// ---------------------------------------------------------------------------
// Launch contract — inputs resolved BY ELEMENT COUNT (robust to whether the
// scalar `out_size` occupies an input slot):
//   edge_features:  T*E = 67108864 f32
//   sparse_indices: E*2 = 16777216 i32
//   kernel:         T*F = 512 f32
//   bias:           F   = 64 f32
// Output: N*F f32.
// ---------------------------------------------------------------------------
extern "C" void kernel_launch(void* const* d_in, const int* in_sizes, int n_in,
                              void* d_out, int out_size) {
    const float* feat = nullptr;
    const int2*  idx  = nullptr;
    const float* kern = nullptr;
    const float* bias = nullptr;

    for (int i = 0; i < n_in; ++i) {
        long long s = in_sizes[i];
        if      (s == (long long)T_ * E_) feat = (const float*)d_in[i];
        else if (s == (long long)2 * E_)  idx  = (const int2*)d_in[i];
        else if (s == T_ * F_)            kern = (const float*)d_in[i];
        else if (s == F_)                 bias = (const float*)d_in[i];
    }
    if (!feat) feat = (const float*)d_in[0];
    if (!idx)  idx  = (const int2*)d_in[1];
    if (!kern) kern = (const float*)d_in[n_in >= 5 ? 3 : 2];
    if (!bias) bias = (const float*)d_in[n_in >= 5 ? 4 : 3];

    float* out = (float*)d_out;
    (void)out_size;

    scatter_kernel<<<E_ / 256, 256>>>(feat, idx);
    // one-shot gemm: N_/2 warps = N_/16 blocks of 256 threads
    gemm_kernel<<<N_ / 16, 256>>>(kern, bias, out);
}

// round 7
// speedup vs baseline: 1.0974x; 1.0974x over previous
#include <cuda_runtime.h>
#include <cstdint>

// Problem constants (fixed by the dataset)
#define T_ 8
#define E_ 8388608
#define N_ 262144
#define F_ 64

// 8 MB scratch for segment sums, layout agg[n][t] row-major (32B per node).
__device__ float g_agg[(size_t)N_ * T_];

// ---------------------------------------------------------------------------
// Kernel 1: zero agg. Runs right before scatter so agg sits in L2 as freshly
// written (dirty) lines — the REDs then never pay a DRAM read-modify-write.
// Plain stores (default policy) on purpose: we WANT these lines resident.
// ---------------------------------------------------------------------------
__global__ void zero_agg_kernel() {
    int i = blockIdx.x * blockDim.x + threadIdx.x;   // N_*T_/4 = 524288 float4s
    reinterpret_cast<float4*>(g_agg)[i] = make_float4(0.f, 0.f, 0.f, 0.f);
}

// ---------------------------------------------------------------------------
// Kernel 2: scatter-add. ONE edge per thread (measured fastest shape).
// 1x int2 index load, 8 coalesced streaming feature loads,
// 2x red.global.add.v4.f32 into L2-resident agg.
// ---------------------------------------------------------------------------
__global__ void scatter_kernel(const float* __restrict__ feat,
                               const int2* __restrict__ idx) {
    int e = blockIdx.x * blockDim.x + threadIdx.x;

    int2 rc = __ldcs(&idx[e]);
    int row = rc.x & (N_ - 1);   // pow2 mask: no-op for valid rows, crash-proof otherwise
    float* dst = g_agg + (size_t)row * T_;

    float f0 = __ldcs(feat + 0 * (size_t)E_ + e);
    float f1 = __ldcs(feat + 1 * (size_t)E_ + e);
    float f2 = __ldcs(feat + 2 * (size_t)E_ + e);
    float f3 = __ldcs(feat + 3 * (size_t)E_ + e);
    asm volatile("red.global.add.v4.f32 [%0], {%1,%2,%3,%4};"
                 :: "l"(dst), "f"(f0), "f"(f1), "f"(f2), "f"(f3) : "memory");

    float f4 = __ldcs(feat + 4 * (size_t)E_ + e);
    float f5 = __ldcs(feat + 5 * (size_t)E_ + e);
    float f6 = __ldcs(feat + 6 * (size_t)E_ + e);
    float f7 = __ldcs(feat + 7 * (size_t)E_ + e);
    asm volatile("red.global.add.v4.f32 [%0], {%1,%2,%3,%4};"
                 :: "l"(dst + 4), "f"(f4), "f"(f5), "f"(f6), "f"(f7) : "memory");
}

// ---------------------------------------------------------------------------
// Kernel 3 (GEMM): out[n,f] = sum_t agg[n,t]*K[t,f] + bias[f].
// 8192 warps; each holds K[8][its f-quad] in 32 registers (loaded ONCE),
// then loops 16 iterations x 2 nodes with the next agg row prefetched before
// computing the current one (hides L2 latency). Per iter per warp:
// 2 uniform LDG.128 + 32 FMA warp-instrs + 1 coalesced STG.128 (.cs).
// ---------------------------------------------------------------------------
#define GEMM_WARPS 8192
#define GEMM_ITERS (N_ / (GEMM_WARPS * 2))   // 16

__global__ void gemm_kernel(const float* __restrict__ kern,
                            const float* __restrict__ bias,
                            float* __restrict__ out) {
    int lane = threadIdx.x & 31;
    int q    = lane & 15;     // f-quad 0..15
    int nsub = lane >> 4;     // 0..1

    float4 k4[T_];
    #pragma unroll
    for (int t = 0; t < T_; ++t)
        k4[t] = __ldg(reinterpret_cast<const float4*>(kern) + t * 16 + q);
    float4 b4 = __ldg(reinterpret_cast<const float4*>(bias) + q);

    int warp = (blockIdx.x * blockDim.x + threadIdx.x) >> 5;   // 0..8191
    int n0 = warp * 2 + nsub;

    const float4* arow = reinterpret_cast<const float4*>(g_agg) + (size_t)n0 * 2;
    float4 a0 = __ldcg(arow);
    float4 a1 = __ldcg(arow + 1);

    #pragma unroll
    for (int i = 0; i < GEMM_ITERS; ++i) {
        int n = n0 + i * GEMM_WARPS * 2;

        float4 na0, na1;
        if (i + 1 < GEMM_ITERS) {
            const float4* nrow = reinterpret_cast<const float4*>(g_agg)
                               + ((size_t)n + GEMM_WARPS * 2) * 2;
            na0 = __ldcg(nrow);
            na1 = __ldcg(nrow + 1);
        }

        float4 acc = b4;
        acc.x = fmaf(a0.x, k4[0].x, acc.x); acc.y = fmaf(a0.x, k4[0].y, acc.y);
        acc.z = fmaf(a0.x, k4[0].z, acc.z); acc.w = fmaf(a0.x, k4[0].w, acc.w);
        acc.x = fmaf(a0.y, k4[1].x, acc.x); acc.y = fmaf(a0.y, k4[1].y, acc.y);
        acc.z = fmaf(a0.y, k4[1].z, acc.z); acc.w = fmaf(a0.y, k4[1].w, acc.w);
        acc.x = fmaf(a0.z, k4[2].x, acc.x); acc.y = fmaf(a0.z, k4[2].y, acc.y);
        acc.z = fmaf(a0.z, k4[2].z, acc.z); acc.w = fmaf(a0.z, k4[2].w, acc.w);
        acc.x = fmaf(a0.w, k4[3].x, acc.x); acc.y = fmaf(a0.w, k4[3].y, acc.y);
        acc.z = fmaf(a0.w, k4[3].z, acc.z); acc.w = fmaf(a0.w, k4[3].w, acc.w);
        acc.x = fmaf(a1.x, k4[4].x, acc.x); acc.y = fmaf(a1.x, k4[4].y, acc.y);
        acc.z = fmaf(a1.x, k4[4].z, acc.z); acc.w = fmaf(a1.x, k4[4].w, acc.w);
        acc.x = fmaf(a1.y, k4[5].x, acc.x); acc.y = fmaf(a1.y, k4[5].y, acc.y);
        acc.z = fmaf(a1.y, k4[5].z, acc.z); acc.w = fmaf(a1.y, k4[5].w, acc.w);
        acc.x = fmaf(a1.z, k4[6].x, acc.x); acc.y = fmaf(a1.z, k4[6].y, acc.y);
        acc.z = fmaf(a1.z, k4[6].z, acc.z); acc.w = fmaf(a1.z, k4[6].w, acc.w);
        acc.x = fmaf(a1.w, k4[7].x, acc.x); acc.y = fmaf(a1.w, k4[7].y, acc.y);
        acc.z = fmaf(a1.w, k4[7].z, acc.z); acc.w = fmaf(a1.w, k4[7].w, acc.w);

        __stcs(reinterpret_cast<float4*>(out) + (size_t)n * 16 + q, acc);

        a0 = na0;
        a1 = na1;
    }
}

// ---------------------------------------------------------------------------
// Launch contract — inputs resolved BY ELEMENT COUNT (robust to whether the
// scalar `out_size` occupies an input slot):
//   edge_features:  T*E = 67108864 f32
//   sparse_indices: E*2 = 16777216 i32
//   kernel:         T*F = 512 f32
//   bias:           F   = 64 f32
// Output: N*F f32.
// ---------------------------------------------------------------------------
extern "C" void kernel_launch(void* const* d_in, const int* in_sizes, int n_in,
                              void* d_out, int out_size) {
    const float* feat = nullptr;
    const int2*  idx  = nullptr;
    const float* kern = nullptr;
    const float* bias = nullptr;

    for (int i = 0; i < n_in; ++i) {
        long long s = in_sizes[i];
        if      (s == (long long)T_ * E_) feat = (const float*)d_in[i];
        else if (s == (long long)2 * E_)  idx  = (const int2*)d_in[i];
        else if (s == T_ * F_)            kern = (const float*)d_in[i];
        else if (s == F_)                 bias = (const float*)d_in[i];
    }
    if (!feat) feat = (const float*)d_in[0];
    if (!idx)  idx  = (const int2*)d_in[1];
    if (!kern) kern = (const float*)d_in[n_in >= 5 ? 3 : 2];
    if (!bias) bias = (const float*)d_in[n_in >= 5 ? 4 : 3];

    float* out = (float*)d_out;
    (void)out_size;

    zero_agg_kernel<<<(N_ * T_ / 4) / 256, 256>>>();
    scatter_kernel<<<E_ / 256, 256>>>(feat, idx);
    gemm_kernel<<<GEMM_WARPS * 32 / 256, 256>>>(kern, bias, out);
}

// round 8
// speedup vs baseline: 1.2698x; 1.1571x over previous
#include <cuda_runtime.h>
#include <cstdint>

// Problem constants (fixed by the dataset)
#define T_ 8
#define E_ 8388608
#define N_ 262144
#define F_ 64

// 8 MB scratch for segment sums, layout agg[n][t] row-major (32B per node).
__device__ float g_agg[(size_t)N_ * T_];

// ---------------------------------------------------------------------------
// Kernel 1: zero agg right before scatter -> agg resident in L2 as dirty
// lines, so the REDs skip the DRAM read-modify-write fetch.
// ---------------------------------------------------------------------------
__global__ void zero_agg_kernel() {
    int i = blockIdx.x * blockDim.x + threadIdx.x;   // N_*T_/4 = 524288 float4s
    reinterpret_cast<float4*>(g_agg)[i] = make_float4(0.f, 0.f, 0.f, 0.f);
}

// ---------------------------------------------------------------------------
// Kernel 2: scatter-add, LANE-PAIR layout: lanes (2j, 2j+1) handle edge j's
// lo/hi feature halves. Each warp covers 16 edges with ONE red.global.add.v4
// instruction whose lane pairs hit adjacent 16B of the same 128B line ->
// ~16 line-wavefronts per RED instruction instead of 32 (halved RED cost if
// L1tex wavefront-per-line is the binding constraint).
// ---------------------------------------------------------------------------
__global__ void scatter_kernel(const float* __restrict__ feat,
                               const int2* __restrict__ idx) {
    int tid  = blockIdx.x * blockDim.x + threadIdx.x;
    int lane = threadIdx.x & 31;
    int h    = lane & 1;                    // 0: t0..3, 1: t4..7
    int e    = (tid >> 5) * 16 + (lane >> 1);   // edge id, < E_

    // lane pairs load the same 8B -> intra-instruction broadcast (free)
    int2 rc = __ldcs(&idx[e]);
    int row = rc.x & (N_ - 1);   // pow2 mask: no-op for valid rows

    size_t plane = (size_t)(4 * h) * E_ + e;
    float f0 = __ldcs(feat + plane);
    float f1 = __ldcs(feat + plane + (size_t)E_);
    float f2 = __ldcs(feat + plane + (size_t)2 * E_);
    float f3 = __ldcs(feat + plane + (size_t)3 * E_);

    float* dst = g_agg + (size_t)row * T_ + 4 * h;
    asm volatile("red.global.add.v4.f32 [%0], {%1,%2,%3,%4};"
                 :: "l"(dst), "f"(f0), "f"(f1), "f"(f2), "f"(f3) : "memory");
}

// ---------------------------------------------------------------------------
// Kernel 3 (GEMM): out[n,f] = sum_t agg[n,t]*K[t,f] + bias[f].
// 8192 warps; K slice in registers (loaded once), 16 iters x 2 nodes with
// next agg row prefetched (hides L2 latency). Unchanged from R7.
// ---------------------------------------------------------------------------
#define GEMM_WARPS 8192
#define GEMM_ITERS (N_ / (GEMM_WARPS * 2))   // 16

__global__ void gemm_kernel(const float* __restrict__ kern,
                            const float* __restrict__ bias,
                            float* __restrict__ out) {
    int lane = threadIdx.x & 31;
    int q    = lane & 15;     // f-quad 0..15
    int nsub = lane >> 4;     // 0..1

    float4 k4[T_];
    #pragma unroll
    for (int t = 0; t < T_; ++t)
        k4[t] = __ldg(reinterpret_cast<const float4*>(kern) + t * 16 + q);
    float4 b4 = __ldg(reinterpret_cast<const float4*>(bias) + q);

    int warp = (blockIdx.x * blockDim.x + threadIdx.x) >> 5;   // 0..8191
    int n0 = warp * 2 + nsub;

    const float4* arow = reinterpret_cast<const float4*>(g_agg) + (size_t)n0 * 2;
    float4 a0 = __ldcg(arow);
    float4 a1 = __ldcg(arow + 1);

    #pragma unroll
    for (int i = 0; i < GEMM_ITERS; ++i) {
        int n = n0 + i * GEMM_WARPS * 2;

        float4 na0, na1;
        if (i + 1 < GEMM_ITERS) {
            const float4* nrow = reinterpret_cast<const float4*>(g_agg)
                               + ((size_t)n + GEMM_WARPS * 2) * 2;
            na0 = __ldcg(nrow);
            na1 = __ldcg(nrow + 1);
        }

        float4 acc = b4;
        acc.x = fmaf(a0.x, k4[0].x, acc.x); acc.y = fmaf(a0.x, k4[0].y, acc.y);
        acc.z = fmaf(a0.x, k4[0].z, acc.z); acc.w = fmaf(a0.x, k4[0].w, acc.w);
        acc.x = fmaf(a0.y, k4[1].x, acc.x); acc.y = fmaf(a0.y, k4[1].y, acc.y);
        acc.z = fmaf(a0.y, k4[1].z, acc.z); acc.w = fmaf(a0.y, k4[1].w, acc.w);
        acc.x = fmaf(a0.z, k4[2].x, acc.x); acc.y = fmaf(a0.z, k4[2].y, acc.y);
        acc.z = fmaf(a0.z, k4[2].z, acc.z); acc.w = fmaf(a0.z, k4[2].w, acc.w);
        acc.x = fmaf(a0.w, k4[3].x, acc.x); acc.y = fmaf(a0.w, k4[3].y, acc.y);
        acc.z = fmaf(a0.w, k4[3].z, acc.z); acc.w = fmaf(a0.w, k4[3].w, acc.w);
        acc.x = fmaf(a1.x, k4[4].x, acc.x); acc.y = fmaf(a1.x, k4[4].y, acc.y);
        acc.z = fmaf(a1.x, k4[4].z, acc.z); acc.w = fmaf(a1.x, k4[4].w, acc.w);
        acc.x = fmaf(a1.y, k4[5].x, acc.x); acc.y = fmaf(a1.y, k4[5].y, acc.y);
        acc.z = fmaf(a1.y, k4[5].z, acc.z); acc.w = fmaf(a1.y, k4[5].w, acc.w);
        acc.x = fmaf(a1.z, k4[6].x, acc.x); acc.y = fmaf(a1.z, k4[6].y, acc.y);
        acc.z = fmaf(a1.z, k4[6].z, acc.z); acc.w = fmaf(a1.z, k4[6].w, acc.w);
        acc.x = fmaf(a1.w, k4[7].x, acc.x); acc.y = fmaf(a1.w, k4[7].y, acc.y);
        acc.z = fmaf(a1.w, k4[7].z, acc.z); acc.w = fmaf(a1.w, k4[7].w, acc.w);

        __stcs(reinterpret_cast<float4*>(out) + (size_t)n * 16 + q, acc);

        a0 = na0;
        a1 = na1;
    }
}

// ---------------------------------------------------------------------------
// Launch contract — inputs resolved BY ELEMENT COUNT (robust to whether the
// scalar `out_size` occupies an input slot):
//   edge_features:  T*E = 67108864 f32
//   sparse_indices: E*2 = 16777216 i32
//   kernel:         T*F = 512 f32
//   bias:           F   = 64 f32
// Output: N*F f32.
// ---------------------------------------------------------------------------
extern "C" void kernel_launch(void* const* d_in, const int* in_sizes, int n_in,
                              void* d_out, int out_size) {
    const float* feat = nullptr;
    const int2*  idx  = nullptr;
    const float* kern = nullptr;
    const float* bias = nullptr;

    for (int i = 0; i < n_in; ++i) {
        long long s = in_sizes[i];
        if      (s == (long long)T_ * E_) feat = (const float*)d_in[i];
        else if (s == (long long)2 * E_)  idx  = (const int2*)d_in[i];
        else if (s == T_ * F_)            kern = (const float*)d_in[i];
        else if (s == F_)                 bias = (const float*)d_in[i];
    }
    if (!feat) feat = (const float*)d_in[0];
    if (!idx)  idx  = (const int2*)d_in[1];
    if (!kern) kern = (const float*)d_in[n_in >= 5 ? 3 : 2];
    if (!bias) bias = (const float*)d_in[n_in >= 5 ? 4 : 3];

    float* out = (float*)d_out;
    (void)out_size;

    zero_agg_kernel<<<(N_ * T_ / 4) / 256, 256>>>();
    // lane-pair scatter: 2 threads per edge -> E_*2 threads total
    scatter_kernel<<<(E_ * 2) / 256, 256>>>(feat, idx);
    gemm_kernel<<<GEMM_WARPS * 32 / 256, 256>>>(kern, bias, out);
}

// round 9
// speedup vs baseline: 1.4319x; 1.1277x over previous
#include <cuda_runtime.h>
#include <cstdint>

// Problem constants (fixed by the dataset)
#define T_ 8
#define E_ 8388608
#define N_ 262144
#define F_ 64

// 8 MB scratch for segment sums, layout agg[n][t] row-major (32B per node).
__device__ float g_agg[(size_t)N_ * T_];

// ---------------------------------------------------------------------------
// Kernel 1: zero agg right before scatter -> agg resident in L2 as dirty
// lines, so the REDs skip the DRAM read-modify-write fetch.
// ---------------------------------------------------------------------------
__global__ void zero_agg_kernel() {
    int i = blockIdx.x * blockDim.x + threadIdx.x;   // N_*T_/4 = 524288 float4s
    reinterpret_cast<float4*>(g_agg)[i] = make_float4(0.f, 0.f, 0.f, 0.f);
}

// ---------------------------------------------------------------------------
// Kernel 2: scatter-add. Warp = 32 edges. Lane pair (2p, 2p+1) handles edges
// eA=base+2p, eB=eA+1: even lane covers feature planes 0..3, odd lane 4..7,
// each loading float2 {eA,eB} per plane (fully-consumed 128B lines -> load
// wavefronts halved vs R8). Rows swapped within the pair via SHFL. Two
// red.global.add.v4.f32 per lane; each RED instruction keeps the lane-pair
// same-line pattern (~16 lines/instr), matching R8's winning RED shape.
// ---------------------------------------------------------------------------
__global__ void scatter_kernel(const float* __restrict__ feat,
                               const int2* __restrict__ idx) {
    int tid   = blockIdx.x * blockDim.x + threadIdx.x;
    int lane  = threadIdx.x & 31;
    int h     = lane & 1;                 // 0: planes 0..3, 1: planes 4..7
    int ebase = (tid >> 5) * 32;          // warp's first edge
    int eA    = ebase + (lane & ~1);      // pair's even edge

    // coalesced: lane i loads idx[ebase+i] (256B/warp)
    int2 rc = __ldcs(&idx[ebase + lane]);
    int row = rc.x & (N_ - 1);            // pow2 mask: no-op for valid rows

    // exchange rows within the lane pair
    int rA = __shfl_sync(0xffffffffu, row, lane & ~1);
    int rB = __shfl_sync(0xffffffffu, row, lane | 1);

    // 4 float2 loads: planes 4h..4h+3 at edges {eA, eA+1}
    size_t plane = (size_t)(4 * h) * E_ + eA;
    float2 l0 = __ldcs(reinterpret_cast<const float2*>(feat + plane));
    float2 l1 = __ldcs(reinterpret_cast<const float2*>(feat + plane + (size_t)E_));
    float2 l2 = __ldcs(reinterpret_cast<const float2*>(feat + plane + (size_t)2 * E_));
    float2 l3 = __ldcs(reinterpret_cast<const float2*>(feat + plane + (size_t)3 * E_));

    // edge eA: x components
    float* dA = g_agg + (size_t)rA * T_ + 4 * h;
    asm volatile("red.global.add.v4.f32 [%0], {%1,%2,%3,%4};"
                 :: "l"(dA), "f"(l0.x), "f"(l1.x), "f"(l2.x), "f"(l3.x) : "memory");

    // edge eB: y components
    float* dB = g_agg + (size_t)rB * T_ + 4 * h;
    asm volatile("red.global.add.v4.f32 [%0], {%1,%2,%3,%4};"
                 :: "l"(dB), "f"(l0.y), "f"(l1.y), "f"(l2.y), "f"(l3.y) : "memory");
}

// ---------------------------------------------------------------------------
// Kernel 3 (GEMM): out[n,f] = sum_t agg[n,t]*K[t,f] + bias[f].
// 8192 warps; K slice in registers (loaded once), 16 iters x 2 nodes with
// next agg row prefetched (hides L2 latency). Unchanged from R8.
// ---------------------------------------------------------------------------
#define GEMM_WARPS 8192
#define GEMM_ITERS (N_ / (GEMM_WARPS * 2))   // 16

__global__ void gemm_kernel(const float* __restrict__ kern,
                            const float* __restrict__ bias,
                            float* __restrict__ out) {
    int lane = threadIdx.x & 31;
    int q    = lane & 15;     // f-quad 0..15
    int nsub = lane >> 4;     // 0..1

    float4 k4[T_];
    #pragma unroll
    for (int t = 0; t < T_; ++t)
        k4[t] = __ldg(reinterpret_cast<const float4*>(kern) + t * 16 + q);
    float4 b4 = __ldg(reinterpret_cast<const float4*>(bias) + q);

    int warp = (blockIdx.x * blockDim.x + threadIdx.x) >> 5;   // 0..8191
    int n0 = warp * 2 + nsub;

    const float4* arow = reinterpret_cast<const float4*>(g_agg) + (size_t)n0 * 2;
    float4 a0 = __ldcg(arow);
    float4 a1 = __ldcg(arow + 1);

    #pragma unroll
    for (int i = 0; i < GEMM_ITERS; ++i) {
        int n = n0 + i * GEMM_WARPS * 2;

        float4 na0, na1;
        if (i + 1 < GEMM_ITERS) {
            const float4* nrow = reinterpret_cast<const float4*>(g_agg)
                               + ((size_t)n + GEMM_WARPS * 2) * 2;
            na0 = __ldcg(nrow);
            na1 = __ldcg(nrow + 1);
        }

        float4 acc = b4;
        acc.x = fmaf(a0.x, k4[0].x, acc.x); acc.y = fmaf(a0.x, k4[0].y, acc.y);
        acc.z = fmaf(a0.x, k4[0].z, acc.z); acc.w = fmaf(a0.x, k4[0].w, acc.w);
        acc.x = fmaf(a0.y, k4[1].x, acc.x); acc.y = fmaf(a0.y, k4[1].y, acc.y);
        acc.z = fmaf(a0.y, k4[1].z, acc.z); acc.w = fmaf(a0.y, k4[1].w, acc.w);
        acc.x = fmaf(a0.z, k4[2].x, acc.x); acc.y = fmaf(a0.z, k4[2].y, acc.y);
        acc.z = fmaf(a0.z, k4[2].z, acc.z); acc.w = fmaf(a0.z, k4[2].w, acc.w);
        acc.x = fmaf(a0.w, k4[3].x, acc.x); acc.y = fmaf(a0.w, k4[3].y, acc.y);
        acc.z = fmaf(a0.w, k4[3].z, acc.z); acc.w = fmaf(a0.w, k4[3].w, acc.w);
        acc.x = fmaf(a1.x, k4[4].x, acc.x); acc.y = fmaf(a1.x, k4[4].y, acc.y);
        acc.z = fmaf(a1.x, k4[4].z, acc.z); acc.w = fmaf(a1.x, k4[4].w, acc.w);
        acc.x = fmaf(a1.y, k4[5].x, acc.x); acc.y = fmaf(a1.y, k4[5].y, acc.y);
        acc.z = fmaf(a1.y, k4[5].z, acc.z); acc.w = fmaf(a1.y, k4[5].w, acc.w);
        acc.x = fmaf(a1.z, k4[6].x, acc.x); acc.y = fmaf(a1.z, k4[6].y, acc.y);
        acc.z = fmaf(a1.z, k4[6].z, acc.z); acc.w = fmaf(a1.z, k4[6].w, acc.w);
        acc.x = fmaf(a1.w, k4[7].x, acc.x); acc.y = fmaf(a1.w, k4[7].y, acc.y);
        acc.z = fmaf(a1.w, k4[7].z, acc.z); acc.w = fmaf(a1.w, k4[7].w, acc.w);

        __stcs(reinterpret_cast<float4*>(out) + (size_t)n * 16 + q, acc);

        a0 = na0;
        a1 = na1;
    }
}

// ---------------------------------------------------------------------------
// Launch contract — inputs resolved BY ELEMENT COUNT (robust to whether the
// scalar `out_size` occupies an input slot):
//   edge_features:  T*E = 67108864 f32
//   sparse_indices: E*2 = 16777216 i32
//   kernel:         T*F = 512 f32
//   bias:           F   = 64 f32
// Output: N*F f32.
// ---------------------------------------------------------------------------
extern "C" void kernel_launch(void* const* d_in, const int* in_sizes, int n_in,
                              void* d_out, int out_size) {
    const float* feat = nullptr;
    const int2*  idx  = nullptr;
    const float* kern = nullptr;
    const float* bias = nullptr;

    for (int i = 0; i < n_in; ++i) {
        long long s = in_sizes[i];
        if      (s == (long long)T_ * E_) feat = (const float*)d_in[i];
        else if (s == (long long)2 * E_)  idx  = (const int2*)d_in[i];
        else if (s == T_ * F_)            kern = (const float*)d_in[i];
        else if (s == F_)                 bias = (const float*)d_in[i];
    }
    if (!feat) feat = (const float*)d_in[0];
    if (!idx)  idx  = (const int2*)d_in[1];
    if (!kern) kern = (const float*)d_in[n_in >= 5 ? 3 : 2];
    if (!bias) bias = (const float*)d_in[n_in >= 5 ? 4 : 3];

    float* out = (float*)d_out;
    (void)out_size;

    zero_agg_kernel<<<(N_ * T_ / 4) / 256, 256>>>();
    // 1 thread per edge, 32 edges per warp
    scatter_kernel<<<E_ / 256, 256>>>(feat, idx);
    gemm_kernel<<<GEMM_WARPS * 32 / 256, 256>>>(kern, bias, out);
}